// round 1
// baseline (speedup 1.0000x reference)
#include <cuda_runtime.h>
#include <math.h>

#define BSZ 512
#define DSZ 256
#define APB 4            // anchors per block
#define EPSF 1e-8f
#define MARGINF 0.3f
#define UWF 0.05f

// scratch (no cudaMalloc allowed)
__device__ float g_Et[DSZ * BSZ];     // E^T: [d][b]
__device__ float g_loss[BSZ];
__device__ float g_validf[BSZ];
__device__ float g_usum[BSZ];

// ---------------------------------------------------------------------------
// K0: transpose E[B][D] -> g_Et[D][B]
// ---------------------------------------------------------------------------
__global__ void k_transpose(const float* __restrict__ E) {
    __shared__ float tile[32][33];
    int x = blockIdx.x * 32 + threadIdx.x;   // d
    int y = blockIdx.y * 32 + threadIdx.y;   // b
#pragma unroll
    for (int m = 0; m < 32; m += 8)
        tile[threadIdx.y + m][threadIdx.x] = E[(y + m) * DSZ + x];
    __syncthreads();
    int xo = blockIdx.y * 32 + threadIdx.x;  // b
    int yo = blockIdx.x * 32 + threadIdx.y;  // d
#pragma unroll
    for (int m = 0; m < 32; m += 8)
        g_Et[(yo + m) * BSZ + xo] = tile[threadIdx.x][threadIdx.y + m];
}

// ---------------------------------------------------------------------------
// K1: per-anchor distance row via Gram trick + hardest pos/neg mining +
//     dist_unc at the 2 selected pairs + per-anchor u-sum.
//     grid = BSZ/APB blocks, 256 threads. Thread t owns columns j=t and j=t+256.
// ---------------------------------------------------------------------------
__global__ __launch_bounds__(256) void k_mine(const float* __restrict__ E,
                                              const float* __restrict__ U,
                                              const int*   __restrict__ L) {
    const int t = threadIdx.x;
    const int i0 = blockIdx.x * APB;

    __shared__ float se[APB][DSZ];      // anchor embedding rows
    __shared__ int   slab[BSZ];
    __shared__ float s_anorm[APB];
    __shared__ float cv[2 * APB][256];  // candidate values (2a=pos/max, 2a+1=neg/min)
    __shared__ int   ci[2 * APB][256];  // candidate indices
    __shared__ int   s_j[2 * APB];
    __shared__ float s_d[2 * APB];
    __shared__ float s_w[2 * APB];      // weighted diff^2 sums
    __shared__ float s_us2[2 * APB];    // u-sum partials (2 per anchor)

#pragma unroll
    for (int a = 0; a < APB; a++) se[a][t] = E[(i0 + a) * DSZ + t];
    slab[t]       = L[t];
    slab[t + 256] = L[t + 256];
    __syncthreads();

    const int j1 = t, j2 = t + 256;
    float acc1[APB], acc2[APB];
#pragma unroll
    for (int a = 0; a < APB; a++) { acc1[a] = 0.f; acc2[a] = 0.f; }
    float n1 = 0.f, n2 = 0.f;

#pragma unroll 8
    for (int d = 0; d < DSZ; d++) {
        float e1 = g_Et[d * BSZ + j1];
        float e2 = g_Et[d * BSZ + j2];
        n1 = fmaf(e1, e1, n1);
        n2 = fmaf(e2, e2, n2);
#pragma unroll
        for (int a = 0; a < APB; a++) {
            float ea = se[a][d];           // smem broadcast
            acc1[a] = fmaf(ea, e1, acc1[a]);
            acc2[a] = fmaf(ea, e2, acc2[a]);
        }
    }

    // publish anchor norms (thread owning j == anchor index)
#pragma unroll
    for (int a = 0; a < APB; a++) {
        int ia = i0 + a;
        if (j1 == ia) s_anorm[a] = n1;
        if (j2 == ia) s_anorm[a] = n2;
    }
    __syncthreads();

    const int lab1 = slab[j1], lab2 = slab[j2];
#pragma unroll
    for (int a = 0; a < APB; a++) {
        const int ia = i0 + a;
        const int laba = slab[ia];
        const float na = s_anorm[a];
        float d2a = fmaxf(na + n1 - 2.f * acc1[a], 0.f);
        float d2b = fmaxf(na + n2 - 2.f * acc2[a], 0.f);
        float dist1 = sqrtf(d2a) + EPSF;
        float dist2 = sqrtf(d2b) + EPSF;

        // hardest positive: max dist among same-label, j != i  (ties -> first idx)
        float pv1 = (lab1 == laba && j1 != ia) ? dist1 : -1e30f;
        float pv2 = (lab2 == laba && j2 != ia) ? dist2 : -1e30f;
        float pv; int pj;
        if (pv1 >= pv2) { pv = pv1; pj = j1; } else { pv = pv2; pj = j2; }
        cv[2 * a][t] = pv; ci[2 * a][t] = pj;

        // hardest negative: min dist among different-label (ties -> first idx)
        float nv1 = (lab1 != laba) ? dist1 : 1e30f;
        float nv2 = (lab2 != laba) ? dist2 : 1e30f;
        float nv; int nj;
        if (nv1 <= nv2) { nv = nv1; nj = j1; } else { nv = nv2; nj = j2; }
        cv[2 * a + 1][t] = nv; ci[2 * a + 1][t] = nj;
    }
    __syncthreads();

    const int w = t >> 5, lane = t & 31;

    // each warp reduces one (anchor, pos/neg) candidate array of 256 entries
    {
        const bool ismax = ((w & 1) == 0);
        float bv = cv[w][lane];
        int   bj = ci[w][lane];
#pragma unroll
        for (int m = 1; m < 8; m++) {
            float v = cv[w][lane + 32 * m];
            int  jx = ci[w][lane + 32 * m];
            bool better = ismax ? (v > bv || (v == bv && jx < bj))
                                : (v < bv || (v == bv && jx < bj));
            if (better) { bv = v; bj = jx; }
        }
#pragma unroll
        for (int off = 16; off; off >>= 1) {
            float v = __shfl_down_sync(0xffffffffu, bv, off);
            int  jx = __shfl_down_sync(0xffffffffu, bj, off);
            bool better = ismax ? (v > bv || (v == bv && jx < bj))
                                : (v < bv || (v == bv && jx < bj));
            if (better) { bv = v; bj = jx; }
        }
        if (lane == 0) { s_j[w] = bj; s_d[w] = bv; }
    }
    __syncthreads();

    // phase 2: warp w computes wsum = sum_d u_i^2 * (e_i - e_j)^2 for its pair,
    //          plus half of the anchor's clipped-u row sum.
    {
        const int a = w >> 1;
        const int ia = i0 + a;
        const int jx = s_j[w];
        float s = 0.f, us = 0.f;
#pragma unroll
        for (int k = 0; k < 8; k++) {
            int d = lane + 32 * k;
            float uu = U[ia * DSZ + d];
            uu = fminf(fmaxf(uu, 1e-6f), 1.0f);       // clip; also maps NaN->1e-6
            float diff = se[a][d] - E[jx * DSZ + d];
            s = fmaf(uu * uu, diff * diff, s);
            if ((k >> 2) == (w & 1)) us += uu;        // each warp sums half the row
        }
#pragma unroll
        for (int off = 16; off; off >>= 1) {
            s  += __shfl_down_sync(0xffffffffu, s, off);
            us += __shfl_down_sync(0xffffffffu, us, off);
        }
        if (lane == 0) { s_w[w] = s; s_us2[w] = us; }
    }
    __syncthreads();

    // phase 3: per-anchor loss
    if (t < APB) {
        const int a = t;
        const int ia = i0 + a;
        float dp = s_d[2 * a], dn = s_d[2 * a + 1];
        bool vp = (dp != -1e30f), vn = (dn != 1e30f);
        float wp = s_w[2 * a], wn = s_w[2 * a + 1];
        float up = sqrtf(wp / (dp * dp) + EPSF);
        float un = sqrtf(wn / (dn * dn) + EPSF);
        float sig = sqrtf(up * up + un * un + EPSF);
        float me = MARGINF + UWF * sig;
        float z = (dp - dn + me) / sig;
        float sp = fmaxf(z, 0.f) + log1pf(expf(-fabsf(z)));
        float per = sig * sp;
        bool valid = vp && vn;
        g_loss[ia]   = valid ? per : 0.f;
        g_validf[ia] = valid ? 1.f : 0.f;
        g_usum[ia]   = s_us2[2 * a] + s_us2[2 * a + 1];
    }
}

// ---------------------------------------------------------------------------
// K2: final reduction -> scalar
// ---------------------------------------------------------------------------
__global__ void k_final(float* __restrict__ out) {
    __shared__ float sl[BSZ], sv[BSZ], su[BSZ];
    int t = threadIdx.x;
    sl[t] = g_loss[t];
    sv[t] = g_validf[t];
    su[t] = g_usum[t];
    __syncthreads();
    for (int off = 256; off; off >>= 1) {
        if (t < off) {
            sl[t] += sl[t + off];
            sv[t] += sv[t + off];
            su[t] += su[t + off];
        }
        __syncthreads();
    }
    if (t == 0) {
        float nv = fmaxf(sv[0], 1.0f);
        float total = sl[0] / nv + UWF * (su[0] / (float)(BSZ * DSZ));
        if (isnan(total) || isinf(total)) total = 0.f;
        out[0] = total;
    }
}

// ---------------------------------------------------------------------------
extern "C" void kernel_launch(void* const* d_in, const int* in_sizes, int n_in,
                              void* d_out, int out_size) {
    const float* E = (const float*)d_in[0];
    const float* U = (const float*)d_in[1];
    const int*   L = (const int*)d_in[2];
    float* out = (float*)d_out;

    dim3 tb(32, 8);
    dim3 tg(DSZ / 32, BSZ / 32);
    k_transpose<<<tg, tb>>>(E);
    k_mine<<<BSZ / APB, 256>>>(E, U, L);
    k_final<<<1, BSZ>>>(out);
}

// round 2
// speedup vs baseline: 1.9482x; 1.9482x over previous
#include <cuda_runtime.h>
#include <math.h>

#define BSZ 512
#define DSZ 256
#define EPSF 1e-8f
#define MARGINF 0.3f
#define UWF 0.05f

// scratch (no cudaMalloc allowed)
__device__ float g_norm[BSZ];
__device__ float g_dist[BSZ * BSZ];
__device__ float g_loss[BSZ];
__device__ float g_validf[BSZ];
__device__ float g_usum[BSZ];

// ---------------------------------------------------------------------------
// K0: row norms  |e_i|^2   (grid 64, block 256 = 8 warps, warp per row)
// ---------------------------------------------------------------------------
__global__ __launch_bounds__(256) void k_norm(const float4* __restrict__ E4) {
    const int w = threadIdx.x >> 5, lane = threadIdx.x & 31;
    const int row = blockIdx.x * 8 + w;
    float4 a = E4[row * 64 + lane];
    float4 b = E4[row * 64 + 32 + lane];
    float s = a.x * a.x;
    s = fmaf(a.y, a.y, s); s = fmaf(a.z, a.z, s); s = fmaf(a.w, a.w, s);
    s = fmaf(b.x, b.x, s); s = fmaf(b.y, b.y, s); s = fmaf(b.z, b.z, s);
    s = fmaf(b.w, b.w, s);
#pragma unroll
    for (int off = 16; off; off >>= 1) s += __shfl_down_sync(0xffffffffu, s, off);
    if (lane == 0) g_norm[row] = s;
}

// ---------------------------------------------------------------------------
// K1: pairwise distance matrix via Gram trick.
//     Tile 64 (i) x 32 (j), grid (16 j-tiles, 8 i-tiles) = 128 blocks.
//     256 threads, each computes a 4x2 register tile. K staged in smem
//     (transposed in-block), next chunk prefetched into registers.
// ---------------------------------------------------------------------------
__global__ __launch_bounds__(256) void k_dist(const float* __restrict__ E) {
    __shared__ __align__(16) float As[32][68];  // [d_local][i_local], padded
    __shared__ __align__(16) float Bs[32][34];  // [d_local][j_local], padded

    const int t = threadIdx.x;
    const int i0 = blockIdx.y * 64;
    const int j0 = blockIdx.x * 32;
    const int tx = t & 15;        // j-pair index
    const int ty = t >> 4;        // i-quad index
    const float4* E4 = (const float4*)E;

    // loader lanes
    const int ar = t >> 2;        // 0..63 : i row within tile
    const int aq = t & 3;         // float4 slot (and +4)
    const int br = t >> 3;        // 0..31 : j row within tile
    const int bq = t & 7;         // float4 slot

    float acc[4][2];
#pragma unroll
    for (int r = 0; r < 4; r++) { acc[r][0] = 0.f; acc[r][1] = 0.f; }

    // prefetch chunk 0
    float4 pa0 = E4[(i0 + ar) * 64 + aq];
    float4 pa1 = E4[(i0 + ar) * 64 + aq + 4];
    float4 pb0 = E4[(j0 + br) * 64 + bq];

#pragma unroll 1
    for (int ch = 0; ch < 8; ch++) {
        // stage (transpose) into smem
        As[aq * 4 + 0][ar] = pa0.x;
        As[aq * 4 + 1][ar] = pa0.y;
        As[aq * 4 + 2][ar] = pa0.z;
        As[aq * 4 + 3][ar] = pa0.w;
        As[aq * 4 + 16][ar] = pa1.x;
        As[aq * 4 + 17][ar] = pa1.y;
        As[aq * 4 + 18][ar] = pa1.z;
        As[aq * 4 + 19][ar] = pa1.w;
        Bs[bq * 4 + 0][br] = pb0.x;
        Bs[bq * 4 + 1][br] = pb0.y;
        Bs[bq * 4 + 2][br] = pb0.z;
        Bs[bq * 4 + 3][br] = pb0.w;
        __syncthreads();

        if (ch < 7) {  // prefetch next chunk (hides L2 latency under compute)
            pa0 = E4[(i0 + ar) * 64 + (ch + 1) * 8 + aq];
            pa1 = E4[(i0 + ar) * 64 + (ch + 1) * 8 + aq + 4];
            pb0 = E4[(j0 + br) * 64 + (ch + 1) * 8 + bq];
        }

#pragma unroll
        for (int d = 0; d < 32; d++) {
            float4 a = *(const float4*)&As[d][4 * ty];
            float2 b = *(const float2*)&Bs[d][2 * tx];
            acc[0][0] = fmaf(a.x, b.x, acc[0][0]);
            acc[0][1] = fmaf(a.x, b.y, acc[0][1]);
            acc[1][0] = fmaf(a.y, b.x, acc[1][0]);
            acc[1][1] = fmaf(a.y, b.y, acc[1][1]);
            acc[2][0] = fmaf(a.z, b.x, acc[2][0]);
            acc[2][1] = fmaf(a.z, b.y, acc[2][1]);
            acc[3][0] = fmaf(a.w, b.x, acc[3][0]);
            acc[3][1] = fmaf(a.w, b.y, acc[3][1]);
        }
        __syncthreads();
    }

    // epilogue: dist = sqrt(max(n_i + n_j - 2 dot, 0)) + EPS
    const int i1 = i0 + 4 * ty;
    const int j1 = j0 + 2 * tx;
    const float nj0 = g_norm[j1];
    const float nj1 = g_norm[j1 + 1];
#pragma unroll
    for (int r = 0; r < 4; r++) {
        float ni = g_norm[i1 + r];
        float d0 = sqrtf(fmaxf(ni + nj0 - 2.f * acc[r][0], 0.f)) + EPSF;
        float d1 = sqrtf(fmaxf(ni + nj1 - 2.f * acc[r][1], 0.f)) + EPSF;
        float2 o; o.x = d0; o.y = d1;
        *(float2*)&g_dist[(i1 + r) * BSZ + j1] = o;
    }
}

// ---------------------------------------------------------------------------
// K2: hardest-pos/neg mining per anchor + dist_unc at the 2 selected pairs.
//     grid 128 blocks x 4 anchors, 256 threads.
// ---------------------------------------------------------------------------
__global__ __launch_bounds__(256) void k_mine(const float* __restrict__ E,
                                              const float* __restrict__ U,
                                              const int*   __restrict__ L) {
    const int t = threadIdx.x;
    const int i0 = blockIdx.x * 4;

    __shared__ int   slab[BSZ];
    __shared__ float cv[8][256];
    __shared__ int   ci[8][256];
    __shared__ int   s_j[8];
    __shared__ float s_d[8];
    __shared__ float s_w[8];
    __shared__ float s_us[8];

    slab[t]       = L[t];
    slab[t + 256] = L[t + 256];
    __syncthreads();

    const int j1 = t, j2 = t + 256;
    const int lab1 = slab[j1], lab2 = slab[j2];

#pragma unroll
    for (int a = 0; a < 4; a++) {
        const int ia = i0 + a;
        const int laba = slab[ia];
        const float dist1 = g_dist[ia * BSZ + j1];
        const float dist2 = g_dist[ia * BSZ + j2];

        // hardest positive: max dist, same label, j != i (ties -> lowest idx)
        float pv1 = (lab1 == laba && j1 != ia) ? dist1 : -1e30f;
        float pv2 = (lab2 == laba && j2 != ia) ? dist2 : -1e30f;
        float pv; int pj;
        if (pv1 >= pv2) { pv = pv1; pj = j1; } else { pv = pv2; pj = j2; }
        cv[2 * a][t] = pv; ci[2 * a][t] = pj;

        // hardest negative: min dist, different label (ties -> lowest idx)
        float nv1 = (lab1 != laba) ? dist1 : 1e30f;
        float nv2 = (lab2 != laba) ? dist2 : 1e30f;
        float nv; int nj;
        if (nv1 <= nv2) { nv = nv1; nj = j1; } else { nv = nv2; nj = j2; }
        cv[2 * a + 1][t] = nv; ci[2 * a + 1][t] = nj;
    }
    __syncthreads();

    const int w = t >> 5, lane = t & 31;

    // warp w reduces candidate array w (anchor w/2, pos if w even)
    {
        const bool ismax = ((w & 1) == 0);
        float bv = cv[w][lane];
        int   bj = ci[w][lane];
#pragma unroll
        for (int m = 1; m < 8; m++) {
            float v = cv[w][lane + 32 * m];
            int  jx = ci[w][lane + 32 * m];
            bool better = ismax ? (v > bv || (v == bv && jx < bj))
                                : (v < bv || (v == bv && jx < bj));
            if (better) { bv = v; bj = jx; }
        }
#pragma unroll
        for (int off = 16; off; off >>= 1) {
            float v = __shfl_down_sync(0xffffffffu, bv, off);
            int  jx = __shfl_down_sync(0xffffffffu, bj, off);
            bool better = ismax ? (v > bv || (v == bv && jx < bj))
                                : (v < bv || (v == bv && jx < bj));
            if (better) { bv = v; bj = jx; }
        }
        if (lane == 0) { s_j[w] = bj; s_d[w] = bv; }
    }
    __syncthreads();

    // warp w: W = sum_d u_i^2 (e_i - e_j)^2 for its selected pair,
    //         plus half of the anchor's clipped-u row sum.
    {
        const int a = w >> 1;
        const int ia = i0 + a;
        const int jx = s_j[w];
        float s = 0.f, us = 0.f;
#pragma unroll
        for (int k = 0; k < 8; k++) {
            int d = lane + 32 * k;
            float uu = U[ia * DSZ + d];
            uu = fminf(fmaxf(uu, 1e-6f), 1.0f);        // clip; NaN -> 1e-6
            float diff = E[ia * DSZ + d] - E[jx * DSZ + d];
            s = fmaf(uu * uu, diff * diff, s);
            if ((k >> 2) == (w & 1)) us += uu;         // each warp sums half the row
        }
#pragma unroll
        for (int off = 16; off; off >>= 1) {
            s  += __shfl_down_sync(0xffffffffu, s, off);
            us += __shfl_down_sync(0xffffffffu, us, off);
        }
        if (lane == 0) { s_w[w] = s; s_us[w] = us; }
    }
    __syncthreads();

    // per-anchor loss
    if (t < 4) {
        const int a = t;
        const int ia = i0 + a;
        float dp = s_d[2 * a], dn = s_d[2 * a + 1];
        bool vp = (dp != -1e30f), vn = (dn != 1e30f);
        float wp = s_w[2 * a], wn = s_w[2 * a + 1];
        float up = sqrtf(wp / (dp * dp) + EPSF);
        float un = sqrtf(wn / (dn * dn) + EPSF);
        float sig = sqrtf(up * up + un * un + EPSF);
        float me = MARGINF + UWF * sig;
        float z = (dp - dn + me) / sig;
        float sp = fmaxf(z, 0.f) + log1pf(expf(-fabsf(z)));
        float per = sig * sp;
        bool valid = vp && vn;
        g_loss[ia]   = valid ? per : 0.f;
        g_validf[ia] = valid ? 1.f : 0.f;
        g_usum[ia]   = s_us[2 * a] + s_us[2 * a + 1];
    }
}

// ---------------------------------------------------------------------------
// K3: final reduction -> scalar
// ---------------------------------------------------------------------------
__global__ __launch_bounds__(512) void k_final(float* __restrict__ out) {
    __shared__ float sl[BSZ], sv[BSZ], su[BSZ];
    int t = threadIdx.x;
    sl[t] = g_loss[t];
    sv[t] = g_validf[t];
    su[t] = g_usum[t];
    __syncthreads();
    for (int off = 256; off; off >>= 1) {
        if (t < off) {
            sl[t] += sl[t + off];
            sv[t] += sv[t + off];
            su[t] += su[t + off];
        }
        __syncthreads();
    }
    if (t == 0) {
        float nv = fmaxf(sv[0], 1.0f);
        float total = sl[0] / nv + UWF * (su[0] / (float)(BSZ * DSZ));
        if (isnan(total) || isinf(total)) total = 0.f;
        out[0] = total;
    }
}

// ---------------------------------------------------------------------------
extern "C" void kernel_launch(void* const* d_in, const int* in_sizes, int n_in,
                              void* d_out, int out_size) {
    const float* E = (const float*)d_in[0];
    const float* U = (const float*)d_in[1];
    const int*   L = (const int*)d_in[2];
    float* out = (float*)d_out;

    k_norm<<<64, 256>>>((const float4*)E);
    k_dist<<<dim3(16, 8), 256>>>(E);
    k_mine<<<128, 256>>>(E, U, L);
    k_final<<<1, 512>>>(out);
}

// round 3
// speedup vs baseline: 2.1854x; 1.1217x over previous
#include <cuda_runtime.h>
#include <math.h>
#include <stdint.h>

#define BSZ 512
#define DSZ 256
#define EPSF 1e-8f
#define MARGINF 0.3f
#define UWF 0.05f

// ---------------------------------------------------------------------------
// scratch (__device__ globals; no cudaMalloc allowed)
// ---------------------------------------------------------------------------
__device__ unsigned long long g_pos[BSZ * 16];   // per (anchor, j-tile) packed max candidate
__device__ unsigned long long g_neg[BSZ * 16];   // per (anchor, j-tile) packed min candidate
__device__ float g_bloss[128];
__device__ float g_bvalid[128];
__device__ float g_busum[128];
__device__ unsigned int g_ctr = 0;               // self-wrapping via atomicInc(.,127)

// packed f32x2 FMA: d = a*b + d (lane-wise IEEE fma)
#define FMA2(d, a, b) \
    asm("fma.rn.f32x2 %0, %1, %2, %0;" : "+l"(d) : "l"(a), "l"(b))

__device__ __forceinline__ uint32_t smem_u32(const void* p) {
    uint32_t r;
    asm("{ .reg .u64 t; cvta.to.shared.u64 t, %1; cvt.u32.u64 %0, t; }"
        : "=r"(r) : "l"(p));
    return r;
}

// ---------------------------------------------------------------------------
// K1: 64(i) x 32(j) distance tiles via Gram trick, FFMA2 inner loop,
//     inline row norms, inline per-tile hardest-pos/neg mining.
//     grid (16 j-tiles, 8 i-tiles) = 128 blocks, 256 threads.
// ---------------------------------------------------------------------------
__global__ __launch_bounds__(256) void k_dist_mine(const float* __restrict__ E,
                                                   const int*   __restrict__ L) {
    __shared__ __align__(16) float As[32][68];   // [d_local][i_local]
    __shared__ __align__(16) float Bs[32][34];   // [d_local][j_local]
    __shared__ float sni[64], snj[32];
    __shared__ int   sli[64], slj[32];

    const int t = threadIdx.x;
    const int i0 = blockIdx.y * 64;
    const int j0 = blockIdx.x * 32;
    const int tx = t & 15;        // j-pair index
    const int ty = t >> 4;        // i-quad index
    const float4* E4 = (const float4*)E;

    // loader lanes
    const int ar = t >> 2;        // 0..63 : i row within tile
    const int aq = t & 3;         // float4 slot (and +4)
    const int br = t >> 3;        // 0..31 : j row within tile
    const int bq = t & 7;         // float4 slot

    if (t < 64) sli[t] = L[i0 + t];
    if (t < 32) slj[t] = L[j0 + t];

    // packed accumulators: low half = anchor 4ty, high = 4ty+1 (acc0*), etc.
    uint64_t acc0x = 0, acc0y = 0, acc1x = 0, acc1y = 0;
    float nA = 0.f, nB = 0.f;

    const uint32_t as_base = smem_u32(&As[0][4 * ty]);
    const uint32_t bs_base = smem_u32(&Bs[0][2 * tx]);

    // prefetch chunk 0
    float4 pa0 = E4[(i0 + ar) * 64 + aq];
    float4 pa1 = E4[(i0 + ar) * 64 + aq + 4];
    float4 pb0 = E4[(j0 + br) * 64 + bq];

#pragma unroll 1
    for (int ch = 0; ch < 8; ch++) {
        // inline norm accumulation from prefetched registers
        nA = fmaf(pa0.x, pa0.x, nA); nA = fmaf(pa0.y, pa0.y, nA);
        nA = fmaf(pa0.z, pa0.z, nA); nA = fmaf(pa0.w, pa0.w, nA);
        nA = fmaf(pa1.x, pa1.x, nA); nA = fmaf(pa1.y, pa1.y, nA);
        nA = fmaf(pa1.z, pa1.z, nA); nA = fmaf(pa1.w, pa1.w, nA);
        nB = fmaf(pb0.x, pb0.x, nB); nB = fmaf(pb0.y, pb0.y, nB);
        nB = fmaf(pb0.z, pb0.z, nB); nB = fmaf(pb0.w, pb0.w, nB);

        // stage (transpose) into smem
        As[aq * 4 + 0][ar] = pa0.x;
        As[aq * 4 + 1][ar] = pa0.y;
        As[aq * 4 + 2][ar] = pa0.z;
        As[aq * 4 + 3][ar] = pa0.w;
        As[aq * 4 + 16][ar] = pa1.x;
        As[aq * 4 + 17][ar] = pa1.y;
        As[aq * 4 + 18][ar] = pa1.z;
        As[aq * 4 + 19][ar] = pa1.w;
        Bs[bq * 4 + 0][br] = pb0.x;
        Bs[bq * 4 + 1][br] = pb0.y;
        Bs[bq * 4 + 2][br] = pb0.z;
        Bs[bq * 4 + 3][br] = pb0.w;
        __syncthreads();

        if (ch < 7) {  // prefetch next chunk (hidden under FMA loop)
            pa0 = E4[(i0 + ar) * 64 + (ch + 1) * 8 + aq];
            pa1 = E4[(i0 + ar) * 64 + (ch + 1) * 8 + aq + 4];
            pb0 = E4[(j0 + br) * 64 + (ch + 1) * 8 + bq];
        }

#pragma unroll
        for (int d = 0; d < 32; d++) {
            uint64_t a01, a23, bxy;
            asm("ld.shared.b64 %0, [%1];" : "=l"(a01) : "r"(as_base + d * (68 * 4)));
            asm("ld.shared.b64 %0, [%1];" : "=l"(a23) : "r"(as_base + d * (68 * 4) + 8));
            asm("ld.shared.b64 %0, [%1];" : "=l"(bxy) : "r"(bs_base + d * (34 * 4)));
            uint32_t bxi, byi;
            asm("mov.b64 {%0, %1}, %2;" : "=r"(bxi), "=r"(byi) : "l"(bxy));
            uint64_t bxx, byy;
            asm("mov.b64 %0, {%1, %1};" : "=l"(bxx) : "r"(bxi));
            asm("mov.b64 %0, {%1, %1};" : "=l"(byy) : "r"(byi));
            FMA2(acc0x, a01, bxx);
            FMA2(acc0y, a01, byy);
            FMA2(acc1x, a23, bxx);
            FMA2(acc1y, a23, byy);
        }
        __syncthreads();
    }

    // publish row norms
    nA += __shfl_xor_sync(0xffffffffu, nA, 1);
    nA += __shfl_xor_sync(0xffffffffu, nA, 2);
    if (aq == 0) sni[ar] = nA;
    nB += __shfl_xor_sync(0xffffffffu, nB, 1);
    nB += __shfl_xor_sync(0xffffffffu, nB, 2);
    nB += __shfl_xor_sync(0xffffffffu, nB, 4);
    if (bq == 0) snj[br] = nB;
    __syncthreads();

    // unpack dots: dt[r][c], r = i-row within quad, c = j within pair
    float dt[4][2];
    {
        uint32_t lo, hi;
        asm("mov.b64 {%0, %1}, %2;" : "=r"(lo), "=r"(hi) : "l"(acc0x));
        dt[0][0] = __uint_as_float(lo); dt[1][0] = __uint_as_float(hi);
        asm("mov.b64 {%0, %1}, %2;" : "=r"(lo), "=r"(hi) : "l"(acc0y));
        dt[0][1] = __uint_as_float(lo); dt[1][1] = __uint_as_float(hi);
        asm("mov.b64 {%0, %1}, %2;" : "=r"(lo), "=r"(hi) : "l"(acc1x));
        dt[2][0] = __uint_as_float(lo); dt[3][0] = __uint_as_float(hi);
        asm("mov.b64 {%0, %1}, %2;" : "=r"(lo), "=r"(hi) : "l"(acc1y));
        dt[2][1] = __uint_as_float(lo); dt[3][1] = __uint_as_float(hi);
    }

    const float njx = snj[2 * tx], njy = snj[2 * tx + 1];
    const int   ljx = slj[2 * tx], ljy = slj[2 * tx + 1];
    const int   jgx = j0 + 2 * tx, jgy = jgx + 1;

#pragma unroll
    for (int r = 0; r < 4; r++) {
        const int gi = i0 + 4 * ty + r;
        const int la = sli[4 * ty + r];
        const float nir = sni[4 * ty + r];
        float d0 = sqrtf(fmaxf(nir + njx - 2.f * dt[r][0], 0.f)) + EPSF;
        float d1 = sqrtf(fmaxf(nir + njy - 2.f * dt[r][1], 0.f)) + EPSF;

        // pos: max dist, same label, j != i; tie -> lowest j (encode ~j)
        unsigned long long bp = 0ull;
        if (ljx == la && jgx != gi)
            bp = ((unsigned long long)__float_as_uint(d0) << 32) | (0xFFFFFFFFu - (unsigned)jgx);
        if (ljy == la && jgy != gi) {
            unsigned long long c =
                ((unsigned long long)__float_as_uint(d1) << 32) | (0xFFFFFFFFu - (unsigned)jgy);
            if (c > bp) bp = c;
        }
        // neg: min dist, different label; tie -> lowest j
        unsigned long long bn = ~0ull;
        if (ljx != la)
            bn = ((unsigned long long)__float_as_uint(d0) << 32) | (unsigned)jgx;
        if (ljy != la) {
            unsigned long long c =
                ((unsigned long long)__float_as_uint(d1) << 32) | (unsigned)jgy;
            if (c < bn) bn = c;
        }

#pragma unroll
        for (int off = 8; off; off >>= 1) {
            unsigned long long o = __shfl_down_sync(0xffffffffu, bp, off, 16);
            if (o > bp) bp = o;
            o = __shfl_down_sync(0xffffffffu, bn, off, 16);
            if (o < bn) bn = o;
        }
        if (tx == 0) {
            g_pos[gi * 16 + blockIdx.x] = bp;
            g_neg[gi * 16 + blockIdx.x] = bn;
        }
    }
}

// ---------------------------------------------------------------------------
// K2: per-anchor candidate combine + dist_unc at selected pairs + loss,
//     with last-block final reduction.  grid 128 blocks x 4 anchors.
// ---------------------------------------------------------------------------
__global__ __launch_bounds__(256) void k_finalize(const float* __restrict__ E,
                                                  const float* __restrict__ U,
                                                  float* __restrict__ out) {
    const int t = threadIdx.x;
    const int bid = blockIdx.x;
    const int i0 = bid * 4;
    const int w = t >> 5, lane = t & 31;

    __shared__ int   s_j[8];
    __shared__ float s_d[8];
    __shared__ int   s_v[8];
    __shared__ float s_w[8];
    __shared__ float s_us[8];
    __shared__ float s_al[4], s_av[4], s_au[4];
    __shared__ int   s_islast;
    __shared__ float s_red[12];

    // phase A: warp w combines 16 tile partials for (anchor w/2, side w&1)
    {
        const int a = w >> 1, side = w & 1;
        const int ia = i0 + a;
        unsigned long long p;
        if (side == 0) p = (lane < 16) ? g_pos[ia * 16 + lane] : 0ull;
        else           p = (lane < 16) ? g_neg[ia * 16 + lane] : ~0ull;
#pragma unroll
        for (int off = 16; off; off >>= 1) {
            unsigned long long o = __shfl_down_sync(0xffffffffu, p, off);
            if (side == 0) { if (o > p) p = o; }
            else           { if (o < p) p = o; }
        }
        if (lane == 0) {
            bool valid = (side == 0) ? (p != 0ull) : (p != ~0ull);
            float dv = __uint_as_float((uint32_t)(p >> 32));
            int   jv = (side == 0) ? (int)(0xFFFFFFFFu - (uint32_t)p) : (int)(uint32_t)p;
            s_v[w] = valid ? 1 : 0;
            s_d[w] = dv;
            s_j[w] = valid ? jv : 0;
        }
    }
    __syncthreads();

    // phase B: warp w computes W = sum_d u_i^2 (e_i - e_j)^2 for its pair,
    //          plus half of the anchor's clipped-u row sum.
    {
        const int a = w >> 1;
        const int ia = i0 + a;
        const int jx = s_j[w];
        float s = 0.f, us = 0.f;
#pragma unroll
        for (int k = 0; k < 8; k++) {
            int d = lane + 32 * k;
            float uu = U[ia * DSZ + d];
            uu = fminf(fmaxf(uu, 1e-6f), 1.0f);     // clip; NaN -> 1e-6
            float diff = E[ia * DSZ + d] - E[jx * DSZ + d];
            s = fmaf(uu * uu, diff * diff, s);
            if ((k >> 2) == (w & 1)) us += uu;      // each warp sums half the row
        }
#pragma unroll
        for (int off = 16; off; off >>= 1) {
            s  += __shfl_down_sync(0xffffffffu, s, off);
            us += __shfl_down_sync(0xffffffffu, us, off);
        }
        if (lane == 0) { s_w[w] = s; s_us[w] = us; }
    }
    __syncthreads();

    // phase C: per-anchor loss
    if (t < 4) {
        const int a = t;
        float dp = s_d[2 * a], dn = s_d[2 * a + 1];
        bool valid = s_v[2 * a] && s_v[2 * a + 1];
        float wp = s_w[2 * a], wn = s_w[2 * a + 1];
        float up2 = wp / (dp * dp) + EPSF;
        float un2 = wn / (dn * dn) + EPSF;
        float sig = sqrtf(up2 + un2 + EPSF);
        float me = MARGINF + UWF * sig;
        float z = (dp - dn + me) / sig;
        float sp = fmaxf(z, 0.f) + log1pf(expf(-fabsf(z)));
        s_al[a] = valid ? sig * sp : 0.f;
        s_av[a] = valid ? 1.f : 0.f;
        s_au[a] = s_us[2 * a] + s_us[2 * a + 1];
    }
    __syncthreads();

    if (t == 0) {
        g_bloss[bid]  = s_al[0] + s_al[1] + s_al[2] + s_al[3];
        g_bvalid[bid] = s_av[0] + s_av[1] + s_av[2] + s_av[3];
        g_busum[bid]  = s_au[0] + s_au[1] + s_au[2] + s_au[3];
        __threadfence();
        s_islast = (atomicInc(&g_ctr, 127) == 127) ? 1 : 0;
    }
    __syncthreads();

    if (s_islast) {
        __threadfence();
        float l = 0.f, v = 0.f, u = 0.f;
        if (t < 128) { l = g_bloss[t]; v = g_bvalid[t]; u = g_busum[t]; }
#pragma unroll
        for (int off = 16; off; off >>= 1) {
            l += __shfl_down_sync(0xffffffffu, l, off);
            v += __shfl_down_sync(0xffffffffu, v, off);
            u += __shfl_down_sync(0xffffffffu, u, off);
        }
        if (lane == 0 && w < 4) {
            s_red[w] = l; s_red[4 + w] = v; s_red[8 + w] = u;
        }
        __syncthreads();
        if (t == 0) {
            float L = s_red[0] + s_red[1] + s_red[2] + s_red[3];
            float V = s_red[4] + s_red[5] + s_red[6] + s_red[7];
            float Uu = s_red[8] + s_red[9] + s_red[10] + s_red[11];
            float total = L / fmaxf(V, 1.0f) + UWF * (Uu / (float)(BSZ * DSZ));
            if (isnan(total) || isinf(total)) total = 0.f;
            out[0] = total;
        }
    }
}

// ---------------------------------------------------------------------------
extern "C" void kernel_launch(void* const* d_in, const int* in_sizes, int n_in,
                              void* d_out, int out_size) {
    const float* E = (const float*)d_in[0];
    const float* U = (const float*)d_in[1];
    const int*   L = (const int*)d_in[2];
    float* out = (float*)d_out;

    k_dist_mine<<<dim3(16, 8), 256>>>(E, L);
    k_finalize<<<128, 256>>>(E, U, out);
}